// round 12
// baseline (speedup 1.0000x reference)
#include <cuda_runtime.h>
#include <stdint.h>

#define BB 4
#define NN 2048
#define EE (NN*(NN-1)/2)        // 2,096,128
#define NPAIR (NN/2)            // 1024
#define PAIRS 4                 // pairs per block
#define GX (NPAIR/PAIRS)        // 256
#define NBLKS (GX*BB)           // 1024
#define TPB 256
#define NWARP (TPB/32)

// SMEM stage layout (floats). One stage holds one full pair (rows i2 long, i1 short).
#define S_A2   0                // 2048 ints
#define S_A1   2048             // 1024 ints
#define S_U2   3072             // 2048 floats
#define S_U1   5120             // 1024 floats
#define S_Q2   6144             // 2052 floats (row + up-to-3 head pad, 16B rounded)
#define S_Q1   8196             // 1028 floats
#define STAGE_FLOATS 9224       // 36,896 B per stage (16B multiple)
#define SMEM_BYTES (2 * STAGE_FLOATS * 4)   // 73,792 B

__device__ float g_partial[NBLKS];
__device__ unsigned int g_count = 0;

struct Consts {
    float f, omf;
    float qt00, qt01, qt10, qt11;   // qt[a][x] = lik(x)*pr(a)/ev(a==x)
};

__device__ __forceinline__ uint32_t smem_u32(const void* p)
{
    uint32_t a;
    asm("{ .reg .u64 t; cvta.to.shared.u64 t, %1; cvt.u32.u64 %0, t; }"
        : "=r"(a) : "l"(p));
    return a;
}

__device__ __forceinline__ void cp16(uint32_t dst, const void* src)
{
    asm volatile("cp.async.cg.shared.global [%0], [%1], 16;" :: "r"(dst), "l"(src));
}

__device__ __forceinline__ float edge_term(int a, float uu, float xv, const Consts& c)
{
    const float p1 = a ? c.omf : c.f;            // P(x_t = 1)
    const bool  x  = uu < p1;
    const float q0 = x ? c.qt01 : c.qt00;        // a = 0
    const float q1 = x ? c.qt11 : c.qt10;        // a = 1
    const float qt = a ? q1 : q0;
    // softplus(-|x|) = log1p(exp(-|x|)) via EX2 + LG2
    const float sp = 0.69314718056f * __log2f(1.0f + __expf(-fabsf(xv)));
    return fmaxf(xv, 0.0f) - xv * qt + sp;
}

// Issue all cp.asyncs for one pair into stage buffer at byte base sb, then commit.
__device__ __forceinline__ void stage_pair(
    uint32_t sb,
    const int* __restrict__ a2p, const float* __restrict__ u2p,
    const float* __restrict__ qa2, int cA2, int cQ2,
    const int* __restrict__ a1p, const float* __restrict__ u1p,
    const float* __restrict__ qa1, int cA1, int cQ1, int tid)
{
    for (int x = tid; x < cA2; x += TPB) {       // <= 512 chunks
        cp16(sb + (S_A2 * 4) + x * 16, a2p + x * 4);
        cp16(sb + (S_U2 * 4) + x * 16, u2p + x * 4);
    }
    for (int x = tid; x < cA1; x += TPB) {       // <= 256 chunks
        cp16(sb + (S_A1 * 4) + x * 16, a1p + x * 4);
        cp16(sb + (S_U1 * 4) + x * 16, u1p + x * 4);
    }
    for (int x = tid; x < cQ2; x += TPB)         // <= 513 chunks
        cp16(sb + (S_Q2 * 4) + x * 16, qa2 + x * 4);
    for (int x = tid; x < cQ1; x += TPB)         // <= 257 chunks
        cp16(sb + (S_Q1 * 4) + x * 16, qa1 + x * 4);
    asm volatile("cp.async.commit_group;" ::: "memory");
}

__global__ __launch_bounds__(TPB) void diffusion_fused_kernel(
    const int*   __restrict__ adj,   // [B, N, N] int32
    const int*   __restrict__ t,     // [B]
    const float* __restrict__ u,     // [B, N, N]
    const float* __restrict__ q,     // [B, E]
    float* __restrict__ out)
{
    extern __shared__ float smem[];
    const int b   = blockIdx.y;
    const int tid = threadIdx.x;

    // Per-batch flip probabilities: f = 0.5*(1 - 0.98^(t+1)); t-1 wraps to 999.
    const int tb = t[b];
    const double L2_098 = -0.0291463456595169;   // log2(0.98)
    const float pw  = exp2f((float)((double)(tb + 1) * L2_098));
    const int   tp  = (tb == 0) ? 999 : (tb - 1);
    const float pwp = exp2f((float)((double)(tp + 1) * L2_098));

    Consts c;
    c.f   = 0.5f * (1.0f - pw);
    c.omf = 1.0f - c.f;
    const float fp   = 0.5f * (1.0f - pwp);
    const float omfp = 1.0f - fp;
    const float rf   = __fdividef(1.0f, c.f);
    const float romf = __fdividef(1.0f, c.omf);
    c.qt00 = 0.01f * fp   * romf;
    c.qt01 = 0.99f * fp   * rf;
    c.qt10 = 0.01f * omfp * rf;
    c.qt11 = 0.99f * omfp * romf;

    const size_t bnn = (size_t)b * NN * NN;
    const size_t bee = (size_t)b * EE;
    const int*   adjb = adj + bnn;
    const float* ub   = u + bnn;
    const float* qb   = q + bee;

    const uint32_t sbase = smem_u32(smem);

    // Stage-parameter helper (macro to avoid struct plumbing).
    int  i1v[PAIRS], i2v[PAIRS], r1v[PAIRS], r2v[PAIRS];
    #pragma unroll
    for (int m = 0; m < PAIRS; m++) {
        const int p  = blockIdx.x * PAIRS + m;
        i1v[m] = p;
        i2v[m] = NN - 1 - p;
        const size_t e1 = ((size_t)i1v[m] * (size_t)(i1v[m] - 1)) / 2;
        const size_t e2 = ((size_t)i2v[m] * (size_t)(i2v[m] - 1)) / 2;
        r1v[m] = (int)(e1 & 3);
        r2v[m] = (int)(e2 & 3);
    }

    #define STAGE(mm, bufIdx)                                                      \
    do {                                                                           \
        const int i1 = i1v[mm], i2 = i2v[mm];                                      \
        const size_t e1 = ((size_t)i1 * (size_t)(i1 - 1)) / 2;                     \
        const size_t e2 = ((size_t)i2 * (size_t)(i2 - 1)) / 2;                     \
        const int r1 = r1v[mm], r2 = r2v[mm];                                      \
        const int cA2 = (i2 + 3) >> 2;                                             \
        const int cA1 = (i1 + 3) >> 2;                                             \
        const int cQ2 = (i2 + r2 + 3) >> 2;                                        \
        const int cQ1 = (i1 > 0) ? ((i1 + r1 + 3) >> 2) : 0;                       \
        stage_pair(sbase + (bufIdx) * (STAGE_FLOATS * 4),                          \
                   adjb + (size_t)i2 * NN, ub + (size_t)i2 * NN, qb + e2 - r2,     \
                   cA2, cQ2,                                                       \
                   adjb + (size_t)i1 * NN, ub + (size_t)i1 * NN, qb + e1 - r1,     \
                   cA1, cQ1, tid);                                                 \
    } while (0)

    float s0 = 0.0f, s1 = 0.0f, s2 = 0.0f, s3 = 0.0f;

    STAGE(0, 0);

    #pragma unroll 1
    for (int m = 0; m < PAIRS; m++) {
        if (m + 1 < PAIRS) {
            STAGE(m + 1, (m + 1) & 1);
            asm volatile("cp.async.wait_group 1;" ::: "memory");
        } else {
            asm volatile("cp.async.wait_group 0;" ::: "memory");
        }
        __syncthreads();

        const float* st  = smem + (m & 1) * STAGE_FLOATS;
        const int*   sA2 = (const int*)st + S_A2;
        const int*   sA1 = (const int*)st + S_A1;
        const float* sU2 = st + S_U2;
        const float* sU1 = st + S_U1;
        const float* sQ2 = st + S_Q2 + r2v[m];
        const float* sQ1 = st + S_Q1 + r1v[m];
        const int i1 = i1v[m], i2 = i2v[m];

        #pragma unroll
        for (int k = 0; k < 8; k++) {
            const int j = tid + k * TPB;
            if (j < i2) {
                const float e = edge_term(sA2[j], sU2[j], sQ2[j], c);
                if ((k & 3) == 0) s0 += e;
                else if ((k & 3) == 1) s1 += e;
                else if ((k & 3) == 2) s2 += e;
                else s3 += e;
            }
        }
        #pragma unroll
        for (int k = 0; k < 4; k++) {
            const int j = tid + k * TPB;
            if (j < i1) {
                const float e = edge_term(sA1[j], sU1[j], sQ1[j], c);
                if (k == 0) s0 += e;
                else if (k == 1) s1 += e;
                else if (k == 2) s2 += e;
                else s3 += e;
            }
        }
        __syncthreads();
    }

    float s = (s0 + s1) + (s2 + s3);
    #pragma unroll
    for (int o = 16; o > 0; o >>= 1)
        s += __shfl_xor_sync(0xFFFFFFFFu, s, o);

    __shared__ float wsum[NWARP];
    __shared__ bool  isLast;
    const int wid = tid >> 5, lid = tid & 31;
    if (lid == 0) wsum[wid] = s;
    __syncthreads();

    if (tid == 0) {
        float bs = 0.0f;
        #pragma unroll
        for (int w = 0; w < NWARP; w++) bs += wsum[w];
        g_partial[blockIdx.y * gridDim.x + blockIdx.x] = bs;
        __threadfence();
        unsigned int old = atomicAdd(&g_count, 1u);
        isLast = (old == (unsigned)(NBLKS - 1));
    }
    __syncthreads();

    if (isLast) {
        __shared__ double dsum[TPB];
        double ds = 0.0;
        for (int idx = tid; idx < NBLKS; idx += TPB)
            ds += (double)g_partial[idx];
        dsum[tid] = ds;
        __syncthreads();
        #pragma unroll
        for (int o = TPB / 2; o > 0; o >>= 1) {
            if (tid < o) dsum[tid] += dsum[tid + o];
            __syncthreads();
        }
        if (tid == 0) {
            out[0] = (float)(dsum[0] / ((double)BB * (double)EE));
            g_count = 0;   // reset for next graph replay
        }
    }
}

extern "C" void kernel_launch(void* const* d_in, const int* in_sizes, int n_in,
                              void* d_out, int out_size)
{
    const int*   adj = (const int*)  d_in[0];
    const int*   t   = (const int*)  d_in[1];
    const float* u   = (const float*)d_in[2];
    const float* q   = (const float*)d_in[3];
    float* out = (float*)d_out;

    cudaFuncSetAttribute(diffusion_fused_kernel,
                         cudaFuncAttributeMaxDynamicSharedMemorySize, SMEM_BYTES);
    dim3 grid(GX, BB);
    diffusion_fused_kernel<<<grid, TPB, SMEM_BYTES>>>(adj, t, u, q, out);
}

// round 14
// speedup vs baseline: 1.2589x; 1.2589x over previous
#include <cuda_runtime.h>

#define BB 4
#define NN 2048
#define EE (NN*(NN-1)/2)        // 2,096,128
#define NPAIR (NN/2)            // 1024
#define PAIRS 8                 // pairs per block
#define GX (NPAIR/PAIRS)        // 128
#define NBLKS (GX*BB)           // 512  -> single wave (capacity ~888 CTAs)
#define TPB 256
#define NWARP (TPB/32)

__device__ float g_partial[NBLKS];
__device__ unsigned int g_count = 0;

struct Consts {
    float f, omf;
    float qt00, qt01, qt10, qt11;   // qt[a][x] = lik(x)*pr(a)/ev(a==x)
};

__device__ __forceinline__ float edge_term(int a, float uu, float xv, const Consts& c)
{
    const float p1 = a ? c.omf : c.f;            // P(x_t = 1)
    const bool  x  = uu < p1;
    const float q0 = x ? c.qt01 : c.qt00;        // a = 0
    const float q1 = x ? c.qt11 : c.qt10;        // a = 1
    const float qt = a ? q1 : q0;
    // softplus(-|x|) = log1p(exp(-|x|)) via EX2 + LG2
    const float sp = 0.69314718056f * __log2f(1.0f + __expf(-fabsf(xv)));
    return fmaxf(xv, 0.0f) - xv * qt + sp;
}

// Best-measured mapping (R7): thread tid owns row elements [8*tid, 8*tid+8).
// 12 loads issued straight-line, consumed into 4 independent accumulators.
__device__ __forceinline__ void row_sum(const int*   __restrict__ arow,
                                        const float* __restrict__ urow,
                                        const float* __restrict__ qrow,
                                        int len, int tid, const Consts& c,
                                        float& s0, float& s1, float& s2, float& s3)
{
    const int g = tid * 8;
    if (g + 8 <= len) {
        const int4   a0 = *reinterpret_cast<const int4*>(arow + g);
        const int4   a1 = *reinterpret_cast<const int4*>(arow + g + 4);
        const float4 u0 = *reinterpret_cast<const float4*>(urow + g);
        const float4 u1 = *reinterpret_cast<const float4*>(urow + g + 4);
        const float  x0 = qrow[g + 0], x1 = qrow[g + 1], x2 = qrow[g + 2], x3 = qrow[g + 3];
        const float  x4 = qrow[g + 4], x5 = qrow[g + 5], x6 = qrow[g + 6], x7 = qrow[g + 7];
        s0 += edge_term(a0.x, u0.x, x0, c);
        s1 += edge_term(a0.y, u0.y, x1, c);
        s2 += edge_term(a0.z, u0.z, x2, c);
        s3 += edge_term(a0.w, u0.w, x3, c);
        s0 += edge_term(a1.x, u1.x, x4, c);
        s1 += edge_term(a1.y, u1.y, x5, c);
        s2 += edge_term(a1.z, u1.z, x6, c);
        s3 += edge_term(a1.w, u1.w, x7, c);
    } else if (g < len) {
        float s = 0.0f;
        for (int j = g; j < len; j++)
            s += edge_term(arow[j], urow[j], qrow[j], c);
        s0 += s;
    }
}

__global__ __launch_bounds__(TPB) void diffusion_fused_kernel(
    const int*   __restrict__ adj,   // [B, N, N] int32
    const int*   __restrict__ t,     // [B]
    const float* __restrict__ u,     // [B, N, N]
    const float* __restrict__ q,     // [B, E]
    float* __restrict__ out)
{
    const int b   = blockIdx.y;
    const int tid = threadIdx.x;

    // Per-batch flip probabilities: f = 0.5*(1 - 0.98^(t+1)); t-1 wraps to 999.
    const int tb = t[b];
    const double L2_098 = -0.0291463456595169;   // log2(0.98)
    const float pw  = exp2f((float)((double)(tb + 1) * L2_098));
    const int   tp  = (tb == 0) ? 999 : (tb - 1);
    const float pwp = exp2f((float)((double)(tp + 1) * L2_098));

    Consts c;
    c.f   = 0.5f * (1.0f - pw);
    c.omf = 1.0f - c.f;
    const float fp   = 0.5f * (1.0f - pwp);
    const float omfp = 1.0f - fp;
    const float rf   = __fdividef(1.0f, c.f);
    const float romf = __fdividef(1.0f, c.omf);
    // qt[a][x] = lik(x) * pr(a) / ev(a==x);  ev: equal -> omf, diff -> f
    c.qt00 = 0.01f * fp   * romf;
    c.qt01 = 0.99f * fp   * rf;
    c.qt10 = 0.01f * omfp * rf;
    c.qt11 = 0.99f * omfp * romf;

    const size_t bnn = (size_t)b * NN * NN;
    const size_t bee = (size_t)b * EE;
    const int*   adjb = adj + bnn;
    const float* ub   = u + bnn;
    const float* qb   = q + bee;

    float s0 = 0.0f, s1 = 0.0f, s2 = 0.0f, s3 = 0.0f;

    #pragma unroll 1
    for (int m = 0; m < PAIRS; m++) {
        const int p  = blockIdx.x * PAIRS + m;
        const int i1 = p;              // short row
        const int i2 = NN - 1 - p;     // long row (i1 + i2 = 2047)
        row_sum(adjb + (size_t)i1 * NN, ub + (size_t)i1 * NN,
                qb + ((size_t)i1 * (size_t)(i1 - 1)) / 2, i1, tid, c, s0, s1, s2, s3);
        row_sum(adjb + (size_t)i2 * NN, ub + (size_t)i2 * NN,
                qb + ((size_t)i2 * (size_t)(i2 - 1)) / 2, i2, tid, c, s0, s1, s2, s3);
    }

    float s = (s0 + s1) + (s2 + s3);
    #pragma unroll
    for (int o = 16; o > 0; o >>= 1)
        s += __shfl_xor_sync(0xFFFFFFFFu, s, o);

    __shared__ float wsum[NWARP];
    __shared__ bool  isLast;
    const int wid = tid >> 5, lid = tid & 31;
    if (lid == 0) wsum[wid] = s;
    __syncthreads();

    if (tid == 0) {
        float bs = 0.0f;
        #pragma unroll
        for (int w = 0; w < NWARP; w++) bs += wsum[w];
        g_partial[blockIdx.y * gridDim.x + blockIdx.x] = bs;
        __threadfence();
        unsigned int old = atomicAdd(&g_count, 1u);
        isLast = (old == (unsigned)(NBLKS - 1));
    }
    __syncthreads();

    if (isLast) {
        __shared__ double dsum[TPB];
        double ds = 0.0;
        for (int idx = tid; idx < NBLKS; idx += TPB)
            ds += (double)g_partial[idx];
        dsum[tid] = ds;
        __syncthreads();
        #pragma unroll
        for (int o = TPB / 2; o > 0; o >>= 1) {
            if (tid < o) dsum[tid] += dsum[tid + o];
            __syncthreads();
        }
        if (tid == 0) {
            out[0] = (float)(dsum[0] / ((double)BB * (double)EE));
            g_count = 0;   // reset for next graph replay
        }
    }
}

extern "C" void kernel_launch(void* const* d_in, const int* in_sizes, int n_in,
                              void* d_out, int out_size)
{
    const int*   adj = (const int*)  d_in[0];
    const int*   t   = (const int*)  d_in[1];
    const float* u   = (const float*)d_in[2];
    const float* q   = (const float*)d_in[3];
    float* out = (float*)d_out;

    dim3 grid(GX, BB);
    diffusion_fused_kernel<<<grid, TPB>>>(adj, t, u, q, out);
}